// round 5
// baseline (speedup 1.0000x reference)
#include <cuda_runtime.h>
#include <math.h>

#define Nn 8192
#define Kk 64
#define Dd 512
#define FD 2048   // 4*D

// Scratch (allocation-free device globals)
__device__ float g_P[(size_t)Nn * FD];      // 64 MB: partial chain f@W_L^T (no biases)
__device__ float g_h[2][(size_t)Nn * Dd];   // ping/pong h
__device__ float g_c[(size_t)Nn * Dd];      // cell state
__device__ float g_r[(size_t)Nn * Dd];      // r = a @ G
__device__ float g_a[(size_t)Nn * Kk];      // softmax weights

// ---- XLA EmitFastTanh f32: rational poly, plain mul/add (no FMA), clamp, small-x select ----
__device__ __forceinline__ float tanh_xla(float x) {
    float ax = fabsf(x);
    float xc = fminf(fmaxf(x, -7.90531110763549805f), 7.90531110763549805f);
    float x2 = __fmul_rn(xc, xc);
    float p = -2.76076847742355e-16f;
    p = __fadd_rn(__fmul_rn(p, x2), 2.00018790482477e-13f);
    p = __fadd_rn(__fmul_rn(p, x2), -8.60467152213735e-11f);
    p = __fadd_rn(__fmul_rn(p, x2), 5.12229709037114e-08f);
    p = __fadd_rn(__fmul_rn(p, x2), 1.48572235717979e-05f);
    p = __fadd_rn(__fmul_rn(p, x2), 6.37261928875436e-04f);
    p = __fadd_rn(__fmul_rn(p, x2), 4.89352455891786e-03f);
    float num = __fmul_rn(xc, p);
    float q = 1.19825839466702e-06f;
    q = __fadd_rn(__fmul_rn(q, x2), 1.18534705686654e-04f);
    q = __fadd_rn(__fmul_rn(q, x2), 2.26843463243900e-03f);
    q = __fadd_rn(__fmul_rn(q, x2), 4.89352518554385e-03f);
    float r = __fdiv_rn(num, q);
    return (ax < 0.0004f) ? x : r;
}
// ---- XLA logistic expander: 0.5 + 0.5 * tanh(0.5 * x) ----
__device__ __forceinline__ float sig_xla(float x) {
    return __fadd_rn(0.5f, __fmul_rn(0.5f, tanh_xla(__fmul_rn(0.5f, x))));
}

// ---------------- init: h0 = f, c = 0 ----------------
__global__ void k_init(const float* __restrict__ f) {
    int i = blockIdx.x * 256 + threadIdx.x;
    g_h[0][i] = f[i];
    g_c[i] = 0.f;
}

// ---------------- P[n][j] = serial ascending-k FMA chain of f[n,:512] . W_ih[j,:512] ----------------
// 128x128 tile, 256 threads, 8x8/thread. Each output's chain: k0 tiles ascending, k ascending. No biases.
__global__ __launch_bounds__(256) void k_P(const float* __restrict__ f,
                                           const float* __restrict__ Wih) {
    __shared__ float As[16][128];
    __shared__ float Bs[16][128];
    const int jb = blockIdx.x * 128, mb = blockIdx.y * 128;
    const int tid = threadIdx.x, tx = tid & 15, ty = tid >> 4;
    const int lr = tid >> 2, lk = (tid & 3) << 2;
    float acc[8][8];
#pragma unroll
    for (int i = 0; i < 8; i++)
#pragma unroll
        for (int q = 0; q < 8; q++) acc[i][q] = 0.f;

    for (int k0 = 0; k0 < Dd; k0 += 16) {
        float4 a0 = *(const float4*)&f[(size_t)(mb + lr) * Dd + k0 + lk];
        float4 a1 = *(const float4*)&f[(size_t)(mb + lr + 64) * Dd + k0 + lk];
        float4 b0 = *(const float4*)&Wih[(size_t)(jb + lr) * 1024 + k0 + lk];
        float4 b1 = *(const float4*)&Wih[(size_t)(jb + lr + 64) * 1024 + k0 + lk];
        __syncthreads();
        As[lk + 0][lr] = a0.x; As[lk + 1][lr] = a0.y; As[lk + 2][lr] = a0.z; As[lk + 3][lr] = a0.w;
        As[lk + 0][lr + 64] = a1.x; As[lk + 1][lr + 64] = a1.y; As[lk + 2][lr + 64] = a1.z; As[lk + 3][lr + 64] = a1.w;
        Bs[lk + 0][lr] = b0.x; Bs[lk + 1][lr] = b0.y; Bs[lk + 2][lr] = b0.z; Bs[lk + 3][lr] = b0.w;
        Bs[lk + 0][lr + 64] = b1.x; Bs[lk + 1][lr + 64] = b1.y; Bs[lk + 2][lr + 64] = b1.z; Bs[lk + 3][lr + 64] = b1.w;
        __syncthreads();
#pragma unroll
        for (int k = 0; k < 16; k++) {
            float ar[8], br[8];
            *(float4*)&ar[0] = *(const float4*)&As[k][ty * 8];
            *(float4*)&ar[4] = *(const float4*)&As[k][ty * 8 + 4];
            *(float4*)&br[0] = *(const float4*)&Bs[k][tx * 8];
            *(float4*)&br[4] = *(const float4*)&Bs[k][tx * 8 + 4];
#pragma unroll
            for (int i = 0; i < 8; i++)
#pragma unroll
                for (int q = 0; q < 8; q++) acc[i][q] = fmaf(ar[i], br[q], acc[i][q]);
        }
    }
#pragma unroll
    for (int i = 0; i < 8; i++) {
        int n = mb + ty * 8 + i;
#pragma unroll
        for (int q = 0; q < 8; q++)
            g_P[(size_t)n * FD + jb + tx * 8 + q] = acc[i][q];
    }
}

// ---------------- attention: logits chain + XLA softmax ----------------
// 8 warps/block, warp owns 4 rows; lane owns k=lane and k=lane+32 (XLA warp row-reduce layout).
__global__ __launch_bounds__(256) void k_attn(int cur, const float* __restrict__ G) {
    __shared__ float Gs[Kk * 129];
    const float* __restrict__ h = g_h[cur];
    const int warp = threadIdx.x >> 5, lane = threadIdx.x & 31;
    const int n0 = blockIdx.x * 32 + warp * 4;
    float acc[4][2];
#pragma unroll
    for (int r = 0; r < 4; r++) { acc[r][0] = 0.f; acc[r][1] = 0.f; }

    for (int ch = 0; ch < 4; ch++) {
        __syncthreads();
        for (int e = threadIdx.x; e < Kk * 128; e += 256)
            Gs[(e >> 7) * 129 + (e & 127)] = G[(e >> 7) * Dd + ch * 128 + (e & 127)];
        __syncthreads();
#pragma unroll 2
        for (int d = 0; d < 128; d++) {      // ascending k chain (ch-major, d-minor => global ascending)
            float w0 = Gs[lane * 129 + d];
            float w1 = Gs[(lane + 32) * 129 + d];
#pragma unroll
            for (int r = 0; r < 4; r++) {
                float hv = h[(size_t)(n0 + r) * Dd + ch * 128 + d];
                acc[r][0] = fmaf(hv, w0, acc[r][0]);
                acc[r][1] = fmaf(hv, w1, acc[r][1]);
            }
        }
    }
#pragma unroll
    for (int r = 0; r < 4; r++) {
        // max (order-independent)
        float m = fmaxf(acc[r][0], acc[r][1]);
#pragma unroll
        for (int off = 16; off; off >>= 1) m = fmaxf(m, __shfl_xor_sync(0xffffffffu, m, off));
        float e0 = expf(acc[r][0] - m);       // libdevice expf, as XLA emits
        float e1 = expf(acc[r][1] - m);
        // XLA warp row-reduce bracketing: partial = x[lane] + x[lane+32]; tree 16,8,4,2,1; lane-0 result
        float s = __fadd_rn(e0, e1);
#pragma unroll
        for (int off = 16; off; off >>= 1) s = __fadd_rn(s, __shfl_xor_sync(0xffffffffu, s, off));
        s = __shfl_sync(0xffffffffu, s, 0);   // lane-0 bracketing for everyone
        g_a[(size_t)(n0 + r) * Kk + lane]      = __fdiv_rn(e0, s);
        g_a[(size_t)(n0 + r) * Kk + lane + 32] = __fdiv_rn(e1, s);
    }
}

// ---------------- r = a @ G : serial ascending k=0..63 chain ----------------
__global__ __launch_bounds__(256) void k_r(const float* __restrict__ G) {
    __shared__ float as[64][65];
    const int d0 = blockIdx.x * 128, n0 = blockIdx.y * 64;
    const int tid = threadIdx.x;
    const int d = d0 + (tid & 127), rg = tid >> 7;

    for (int e = tid; e < 64 * 64; e += 256)
        as[e >> 6][e & 63] = g_a[(size_t)(n0 + (e >> 6)) * Kk + (e & 63)];
    __syncthreads();

    float acc[32];
#pragma unroll
    for (int r = 0; r < 32; r++) acc[r] = 0.f;
    for (int k = 0; k < Kk; k++) {
        float gv = G[k * Dd + d];
#pragma unroll
        for (int r = 0; r < 32; r++) acc[r] = fmaf(as[rg * 32 + r][k], gv, acc[r]);
    }
#pragma unroll
    for (int r = 0; r < 32; r++)
        g_r[(size_t)(n0 + rg * 32 + r) * Dd + d] = acc[r];
}

// ---------------- gates + fused LSTM ----------------
// gates = ((x@W_ih^T + b_ih) + h@W_hh^T) + b_hh, with x-chain resumed from g_P.
// Tile: 64 rows x 128 cols (4 gates x 32 dc). Thread: 4 rows x (4 gates x 2 dc).
__global__ __launch_bounds__(256) void k_gates(int cur,
        const float* __restrict__ Whh, const float* __restrict__ Wih,
        const float* __restrict__ bih, const float* __restrict__ bhh,
        const float* __restrict__ f, float* __restrict__ dout, int last) {
    __shared__ float As[16][64];
    __shared__ float Bs[16][128];
    const float* __restrict__ h = g_h[cur];
    float* __restrict__ hout = last ? dout : g_h[cur ^ 1];
    const int dcb = blockIdx.x * 32, mb = blockIdx.y * 64;
    const int tid = threadIdx.x, tx = tid & 15, ty = tid >> 4;
    const int arow = tid >> 2, ak = (tid & 3) << 2;   // A loader: 64 rows x 4k-float4
    const int bj = tid >> 1, bk = (tid & 1) << 3;     // B loader: 128 cols x 8k
    const size_t bjW = (size_t)((bj >> 5) * Dd + dcb + (bj & 31));  // global j for tile col bj

    float acc_h[4][8], acc_x[4][8];
#pragma unroll
    for (int i = 0; i < 4; i++)
#pragma unroll
        for (int q = 0; q < 8; q++) acc_h[i][q] = 0.f;

    // ---- phase 1: h @ W_hh^T, serial ascending k 0..511 ----
    for (int k0 = 0; k0 < Dd; k0 += 16) {
        float4 av = *(const float4*)&h[(size_t)(mb + arow) * Dd + k0 + ak];
        float4 b0 = *(const float4*)&Whh[bjW * Dd + k0 + bk];
        float4 b1 = *(const float4*)&Whh[bjW * Dd + k0 + bk + 4];
        __syncthreads();
        As[ak + 0][arow] = av.x; As[ak + 1][arow] = av.y; As[ak + 2][arow] = av.z; As[ak + 3][arow] = av.w;
        Bs[bk + 0][bj] = b0.x; Bs[bk + 1][bj] = b0.y; Bs[bk + 2][bj] = b0.z; Bs[bk + 3][bj] = b0.w;
        Bs[bk + 4][bj] = b1.x; Bs[bk + 5][bj] = b1.y; Bs[bk + 6][bj] = b1.z; Bs[bk + 7][bj] = b1.w;
        __syncthreads();
#pragma unroll
        for (int k = 0; k < 16; k++) {
            float ar[4], br[8];
            *(float4*)&ar[0] = *(const float4*)&As[k][ty * 4];
#pragma unroll
            for (int g = 0; g < 4; g++)
                *(float2*)&br[g * 2] = *(const float2*)&Bs[k][g * 32 + tx * 2];
#pragma unroll
            for (int i = 0; i < 4; i++)
#pragma unroll
                for (int q = 0; q < 8; q++) acc_h[i][q] = fmaf(ar[i], br[q], acc_h[i][q]);
        }
    }

    // ---- resume x-chain from P, then r-part k 512..1023 ascending ----
#pragma unroll
    for (int i = 0; i < 4; i++) {
        int n = mb + ty * 4 + i;
#pragma unroll
        for (int g = 0; g < 4; g++)
#pragma unroll
            for (int p = 0; p < 2; p++)
                acc_x[i][g * 2 + p] = g_P[(size_t)n * FD + g * Dd + dcb + tx * 2 + p];
    }
    for (int k0 = 0; k0 < Dd; k0 += 16) {
        float4 av = *(const float4*)&g_r[(size_t)(mb + arow) * Dd + k0 + ak];
        float4 b0 = *(const float4*)&Wih[bjW * 1024 + 512 + k0 + bk];
        float4 b1 = *(const float4*)&Wih[bjW * 1024 + 512 + k0 + bk + 4];
        __syncthreads();
        As[ak + 0][arow] = av.x; As[ak + 1][arow] = av.y; As[ak + 2][arow] = av.z; As[ak + 3][arow] = av.w;
        Bs[bk + 0][bj] = b0.x; Bs[bk + 1][bj] = b0.y; Bs[bk + 2][bj] = b0.z; Bs[bk + 3][bj] = b0.w;
        Bs[bk + 4][bj] = b1.x; Bs[bk + 5][bj] = b1.y; Bs[bk + 6][bj] = b1.z; Bs[bk + 7][bj] = b1.w;
        __syncthreads();
#pragma unroll
        for (int k = 0; k < 16; k++) {
            float ar[4], br[8];
            *(float4*)&ar[0] = *(const float4*)&As[k][ty * 4];
#pragma unroll
            for (int g = 0; g < 4; g++)
                *(float2*)&br[g * 2] = *(const float2*)&Bs[k][g * 32 + tx * 2];
#pragma unroll
            for (int i = 0; i < 4; i++)
#pragma unroll
                for (int q = 0; q < 8; q++) acc_x[i][q] = fmaf(ar[i], br[q], acc_x[i][q]);
        }
    }

    // ---- epilogue: ((x + b_ih) + hW) + b_hh, XLA pointwise (no FMA), write c / h ----
#pragma unroll
    for (int i = 0; i < 4; i++) {
        int n = mb + ty * 4 + i;
#pragma unroll
        for (int p = 0; p < 2; p++) {
            int dc = dcb + tx * 2 + p;
            float iv = __fadd_rn(__fadd_rn(__fadd_rn(acc_x[i][0 + p], bih[0 * Dd + dc]), acc_h[i][0 + p]), bhh[0 * Dd + dc]);
            float fv = __fadd_rn(__fadd_rn(__fadd_rn(acc_x[i][2 + p], bih[1 * Dd + dc]), acc_h[i][2 + p]), bhh[1 * Dd + dc]);
            float gv = __fadd_rn(__fadd_rn(__fadd_rn(acc_x[i][4 + p], bih[2 * Dd + dc]), acc_h[i][4 + p]), bhh[2 * Dd + dc]);
            float ov = __fadd_rn(__fadd_rn(__fadd_rn(acc_x[i][6 + p], bih[3 * Dd + dc]), acc_h[i][6 + p]), bhh[3 * Dd + dc]);
            float co = g_c[(size_t)n * Dd + dc];
            float cn = __fadd_rn(__fmul_rn(sig_xla(fv), co), __fmul_rn(sig_xla(iv), tanh_xla(gv)));
            float hn = __fadd_rn(__fmul_rn(sig_xla(ov), tanh_xla(cn)), f[(size_t)n * Dd + dc]);
            g_c[(size_t)n * Dd + dc] = cn;
            hout[(size_t)n * Dd + dc] = hn;
        }
    }
}

extern "C" void kernel_launch(void* const* d_in, const int* in_sizes, int n_in,
                              void* d_out, int out_size) {
    const float* f   = (const float*)d_in[0];
    const float* G   = (const float*)d_in[1];
    const float* Wih = (const float*)d_in[2];
    const float* Whh = (const float*)d_in[3];
    const float* bih = (const float*)d_in[4];
    const float* bhh = (const float*)d_in[5];
    float* out = (float*)d_out;

    k_init<<<(Nn * Dd) / 256, 256>>>(f);
    k_P<<<dim3(FD / 128, Nn / 128), 256>>>(f, Wih);

    for (int s = 0; s < Kk; s++) {
        k_attn<<<Nn / 32, 256>>>(s & 1, G);
        k_r<<<dim3(Dd / 128, Nn / 64), 256>>>(G);
        k_gates<<<dim3(Dd / 32, Nn / 64), 256>>>(s & 1, Whh, Wih, bih, bhh, f, out, s == Kk - 1);
    }
}

// round 6
// speedup vs baseline: 1.1661x; 1.1661x over previous
#include <cuda_runtime.h>
#include <math.h>

#define Nn 8192
#define Kk 64
#define Dd 512
#define FD 2048   // 4*D

// Scratch (allocation-free device globals)
__device__ float g_P[(size_t)Nn * FD];      // 64 MB: partial chain f@W_L^T (no biases)
__device__ float g_hw[(size_t)Nn * FD];     // 64 MB: h@W_hh^T per step
__device__ float g_h[2][(size_t)Nn * Dd];   // ping/pong h
__device__ float g_c[(size_t)Nn * Dd];      // cell state
__device__ float g_r[(size_t)Nn * Dd];      // r = a @ G
__device__ float g_a[(size_t)Nn * Kk];      // softmax weights

// ---- XLA EmitFastTanh f32 (verbatim from passing R5 kernel) ----
__device__ __forceinline__ float tanh_xla(float x) {
    float ax = fabsf(x);
    float xc = fminf(fmaxf(x, -7.90531110763549805f), 7.90531110763549805f);
    float x2 = __fmul_rn(xc, xc);
    float p = -2.76076847742355e-16f;
    p = __fadd_rn(__fmul_rn(p, x2), 2.00018790482477e-13f);
    p = __fadd_rn(__fmul_rn(p, x2), -8.60467152213735e-11f);
    p = __fadd_rn(__fmul_rn(p, x2), 5.12229709037114e-08f);
    p = __fadd_rn(__fmul_rn(p, x2), 1.48572235717979e-05f);
    p = __fadd_rn(__fmul_rn(p, x2), 6.37261928875436e-04f);
    p = __fadd_rn(__fmul_rn(p, x2), 4.89352455891786e-03f);
    float num = __fmul_rn(xc, p);
    float q = 1.19825839466702e-06f;
    q = __fadd_rn(__fmul_rn(q, x2), 1.18534705686654e-04f);
    q = __fadd_rn(__fmul_rn(q, x2), 2.26843463243900e-03f);
    q = __fadd_rn(__fmul_rn(q, x2), 4.89352518554385e-03f);
    float r = __fdiv_rn(num, q);
    return (ax < 0.0004f) ? x : r;
}
__device__ __forceinline__ float sig_xla(float x) {
    return __fadd_rn(0.5f, __fmul_rn(0.5f, tanh_xla(__fmul_rn(0.5f, x))));
}

// ---------------- init: h0 = f, c = 0 ----------------
__global__ void k_init(const float* __restrict__ f) {
    int i = blockIdx.x * 256 + threadIdx.x;
    g_h[0][i] = f[i];
    g_c[i] = 0.f;
}

// ---------------- generic SGEMM: C[m][j] = serial-k chain A[m,:512].B[j,:512] ----------------
// 128x128 tile, 256 threads, 8x8/thread, double-buffered smem, 1 sync/k-tile.
// A = (Aopt ? Aopt : g_h[cur]); B row j at B + j*bstride; C row-major ldc=2048.
__global__ __launch_bounds__(256, 2) void k_gemm(const float* __restrict__ Aopt, int cur,
                                                 const float* __restrict__ B, long bstride,
                                                 float* __restrict__ C) {
    __shared__ float As[2][16][128];
    __shared__ float Bs[2][16][128];
    const float* __restrict__ A = Aopt ? Aopt : g_h[cur];
    const int jb = blockIdx.x * 128, mb = blockIdx.y * 128;
    const int tid = threadIdx.x, tx = tid & 15, ty = tid >> 4;
    const int lrow = tid >> 1, lk = (tid & 1) << 3;   // 128 rows/cols, 8 k-floats each
    float acc[8][8];
#pragma unroll
    for (int i = 0; i < 8; i++)
#pragma unroll
        for (int q = 0; q < 8; q++) acc[i][q] = 0.f;

    const float* Arow = A + (size_t)(mb + lrow) * Dd + lk;
    const float* Brow = B + (size_t)(jb + lrow) * bstride + lk;

    float4 a0 = *(const float4*)(Arow), a1 = *(const float4*)(Arow + 4);
    float4 b0 = *(const float4*)(Brow), b1 = *(const float4*)(Brow + 4);
    As[0][lk + 0][lrow] = a0.x; As[0][lk + 1][lrow] = a0.y; As[0][lk + 2][lrow] = a0.z; As[0][lk + 3][lrow] = a0.w;
    As[0][lk + 4][lrow] = a1.x; As[0][lk + 5][lrow] = a1.y; As[0][lk + 6][lrow] = a1.z; As[0][lk + 7][lrow] = a1.w;
    Bs[0][lk + 0][lrow] = b0.x; Bs[0][lk + 1][lrow] = b0.y; Bs[0][lk + 2][lrow] = b0.z; Bs[0][lk + 3][lrow] = b0.w;
    Bs[0][lk + 4][lrow] = b1.x; Bs[0][lk + 5][lrow] = b1.y; Bs[0][lk + 6][lrow] = b1.z; Bs[0][lk + 7][lrow] = b1.w;
    __syncthreads();

    for (int kt = 0; kt < 32; kt++) {
        const int buf = kt & 1;
        if (kt < 31) {
            a0 = *(const float4*)(Arow + (kt + 1) * 16);
            a1 = *(const float4*)(Arow + (kt + 1) * 16 + 4);
            b0 = *(const float4*)(Brow + (kt + 1) * 16);
            b1 = *(const float4*)(Brow + (kt + 1) * 16 + 4);
        }
#pragma unroll
        for (int k = 0; k < 16; k++) {
            float ar[8], br[8];
            *(float4*)&ar[0] = *(const float4*)&As[buf][k][ty * 8];
            *(float4*)&ar[4] = *(const float4*)&As[buf][k][ty * 8 + 4];
            *(float4*)&br[0] = *(const float4*)&Bs[buf][k][tx * 8];
            *(float4*)&br[4] = *(const float4*)&Bs[buf][k][tx * 8 + 4];
#pragma unroll
            for (int i = 0; i < 8; i++)
#pragma unroll
                for (int q = 0; q < 8; q++) acc[i][q] = fmaf(ar[i], br[q], acc[i][q]);
        }
        if (kt < 31) {
            const int nb = buf ^ 1;
            As[nb][lk + 0][lrow] = a0.x; As[nb][lk + 1][lrow] = a0.y; As[nb][lk + 2][lrow] = a0.z; As[nb][lk + 3][lrow] = a0.w;
            As[nb][lk + 4][lrow] = a1.x; As[nb][lk + 5][lrow] = a1.y; As[nb][lk + 6][lrow] = a1.z; As[nb][lk + 7][lrow] = a1.w;
            Bs[nb][lk + 0][lrow] = b0.x; Bs[nb][lk + 1][lrow] = b0.y; Bs[nb][lk + 2][lrow] = b0.z; Bs[nb][lk + 3][lrow] = b0.w;
            Bs[nb][lk + 4][lrow] = b1.x; Bs[nb][lk + 5][lrow] = b1.y; Bs[nb][lk + 6][lrow] = b1.z; Bs[nb][lk + 7][lrow] = b1.w;
            __syncthreads();
        }
    }
#pragma unroll
    for (int i = 0; i < 8; i++) {
        int n = mb + ty * 8 + i;
#pragma unroll
        for (int q = 0; q < 8; q++)
            C[(size_t)n * FD + jb + tx * 8 + q] = acc[i][q];
    }
}

// ---------------- attention: logits chain + XLA softmax (verbatim R5) ----------------
__global__ __launch_bounds__(256) void k_attn(int cur, const float* __restrict__ G) {
    __shared__ float Gs[Kk * 129];
    const float* __restrict__ h = g_h[cur];
    const int warp = threadIdx.x >> 5, lane = threadIdx.x & 31;
    const int n0 = blockIdx.x * 32 + warp * 4;
    float acc[4][2];
#pragma unroll
    for (int r = 0; r < 4; r++) { acc[r][0] = 0.f; acc[r][1] = 0.f; }

    for (int ch = 0; ch < 4; ch++) {
        __syncthreads();
        for (int e = threadIdx.x; e < Kk * 128; e += 256)
            Gs[(e >> 7) * 129 + (e & 127)] = G[(e >> 7) * Dd + ch * 128 + (e & 127)];
        __syncthreads();
#pragma unroll 2
        for (int d = 0; d < 128; d++) {
            float w0 = Gs[lane * 129 + d];
            float w1 = Gs[(lane + 32) * 129 + d];
#pragma unroll
            for (int r = 0; r < 4; r++) {
                float hv = h[(size_t)(n0 + r) * Dd + ch * 128 + d];
                acc[r][0] = fmaf(hv, w0, acc[r][0]);
                acc[r][1] = fmaf(hv, w1, acc[r][1]);
            }
        }
    }
#pragma unroll
    for (int r = 0; r < 4; r++) {
        float m = fmaxf(acc[r][0], acc[r][1]);
#pragma unroll
        for (int off = 16; off; off >>= 1) m = fmaxf(m, __shfl_xor_sync(0xffffffffu, m, off));
        float e0 = expf(acc[r][0] - m);
        float e1 = expf(acc[r][1] - m);
        float s = __fadd_rn(e0, e1);
#pragma unroll
        for (int off = 16; off; off >>= 1) s = __fadd_rn(s, __shfl_xor_sync(0xffffffffu, s, off));
        s = __shfl_sync(0xffffffffu, s, 0);
        g_a[(size_t)(n0 + r) * Kk + lane]      = __fdiv_rn(e0, s);
        g_a[(size_t)(n0 + r) * Kk + lane + 32] = __fdiv_rn(e1, s);
    }
}

// ---------------- r = a @ G : serial ascending k chain, smem-cached G tile ----------------
// CTA: 32 rows x 128 d. 256 threads = 8 row-groups x 32 d-threads; thread = 4 rows x float4.
__global__ __launch_bounds__(256) void k_r(const float* __restrict__ G) {
    __shared__ float Gs[Kk][128];
    __shared__ float as[32][Kk];
    const int d0 = blockIdx.x * 128, n0 = blockIdx.y * 32;
    const int tid = threadIdx.x;
    const int dthr = tid & 31, rgrp = tid >> 5;

    for (int e = tid; e < Kk * 128; e += 256)
        Gs[e >> 7][e & 127] = G[(size_t)(e >> 7) * Dd + d0 + (e & 127)];
    for (int e = tid; e < 32 * Kk; e += 256)
        as[e >> 6][e & 63] = g_a[(size_t)(n0 + (e >> 6)) * Kk + (e & 63)];
    __syncthreads();

    float4 acc[4];
#pragma unroll
    for (int r = 0; r < 4; r++) { acc[r].x = 0.f; acc[r].y = 0.f; acc[r].z = 0.f; acc[r].w = 0.f; }
    for (int k = 0; k < Kk; k++) {     // ascending k chain per output
        float4 gv = *(const float4*)&Gs[k][dthr * 4];
#pragma unroll
        for (int r = 0; r < 4; r++) {
            float av = as[rgrp * 4 + r][k];
            acc[r].x = fmaf(av, gv.x, acc[r].x);
            acc[r].y = fmaf(av, gv.y, acc[r].y);
            acc[r].z = fmaf(av, gv.z, acc[r].z);
            acc[r].w = fmaf(av, gv.w, acc[r].w);
        }
    }
#pragma unroll
    for (int r = 0; r < 4; r++)
        *(float4*)&g_r[(size_t)(n0 + rgrp * 4 + r) * Dd + d0 + dthr * 4] = acc[r];
}

// ---------------- x-chain GEMM (resumed from g_P) + fused LSTM epilogue ----------------
// Tile 128 rows x (4 gates x 32 dc), 8x8/thread (thread cols = 4 gates x 2 dc).
__global__ __launch_bounds__(256, 2) void k_gx(int cur, const float* __restrict__ Wih,
        const float* __restrict__ bih, const float* __restrict__ bhh,
        const float* __restrict__ f, float* __restrict__ dout, int last) {
    __shared__ float As[2][16][128];
    __shared__ float Bs[2][16][128];
    float* __restrict__ hout = last ? dout : g_h[cur ^ 1];
    const int dcb = blockIdx.x * 32, mb = blockIdx.y * 128;
    const int tid = threadIdx.x, tx = tid & 15, ty = tid >> 4;
    const int lrow = tid >> 1, lk = (tid & 1) << 3;
    const size_t bj = (size_t)((lrow >> 5) * Dd + dcb + (lrow & 31));   // global j for tile col lrow

    const float* Arow = g_r + (size_t)(mb + lrow) * Dd + lk;
    const float* Brow = Wih + bj * 1024 + 512 + lk;

    // resume x-chain from P
    float acc[8][8];
#pragma unroll
    for (int i = 0; i < 8; i++) {
        int n = mb + ty * 8 + i;
#pragma unroll
        for (int g = 0; g < 4; g++) {
            float2 v = *(const float2*)&g_P[(size_t)n * FD + g * Dd + dcb + tx * 2];
            acc[i][g * 2] = v.x; acc[i][g * 2 + 1] = v.y;
        }
    }

    float4 a0 = *(const float4*)(Arow), a1 = *(const float4*)(Arow + 4);
    float4 b0 = *(const float4*)(Brow), b1 = *(const float4*)(Brow + 4);
    As[0][lk + 0][lrow] = a0.x; As[0][lk + 1][lrow] = a0.y; As[0][lk + 2][lrow] = a0.z; As[0][lk + 3][lrow] = a0.w;
    As[0][lk + 4][lrow] = a1.x; As[0][lk + 5][lrow] = a1.y; As[0][lk + 6][lrow] = a1.z; As[0][lk + 7][lrow] = a1.w;
    Bs[0][lk + 0][lrow] = b0.x; Bs[0][lk + 1][lrow] = b0.y; Bs[0][lk + 2][lrow] = b0.z; Bs[0][lk + 3][lrow] = b0.w;
    Bs[0][lk + 4][lrow] = b1.x; Bs[0][lk + 5][lrow] = b1.y; Bs[0][lk + 6][lrow] = b1.z; Bs[0][lk + 7][lrow] = b1.w;
    __syncthreads();

    for (int kt = 0; kt < 32; kt++) {
        const int buf = kt & 1;
        if (kt < 31) {
            a0 = *(const float4*)(Arow + (kt + 1) * 16);
            a1 = *(const float4*)(Arow + (kt + 1) * 16 + 4);
            b0 = *(const float4*)(Brow + (kt + 1) * 16);
            b1 = *(const float4*)(Brow + (kt + 1) * 16 + 4);
        }
#pragma unroll
        for (int k = 0; k < 16; k++) {
            float ar[8], br[8];
            *(float4*)&ar[0] = *(const float4*)&As[buf][k][ty * 8];
            *(float4*)&ar[4] = *(const float4*)&As[buf][k][ty * 8 + 4];
#pragma unroll
            for (int g = 0; g < 4; g++)
                *(float2*)&br[g * 2] = *(const float2*)&Bs[buf][k][g * 32 + tx * 2];
#pragma unroll
            for (int i = 0; i < 8; i++)
#pragma unroll
                for (int q = 0; q < 8; q++) acc[i][q] = fmaf(ar[i], br[q], acc[i][q]);
        }
        if (kt < 31) {
            const int nb = buf ^ 1;
            As[nb][lk + 0][lrow] = a0.x; As[nb][lk + 1][lrow] = a0.y; As[nb][lk + 2][lrow] = a0.z; As[nb][lk + 3][lrow] = a0.w;
            As[nb][lk + 4][lrow] = a1.x; As[nb][lk + 5][lrow] = a1.y; As[nb][lk + 6][lrow] = a1.z; As[nb][lk + 7][lrow] = a1.w;
            Bs[nb][lk + 0][lrow] = b0.x; Bs[nb][lk + 1][lrow] = b0.y; Bs[nb][lk + 2][lrow] = b0.z; Bs[nb][lk + 3][lrow] = b0.w;
            Bs[nb][lk + 4][lrow] = b1.x; Bs[nb][lk + 5][lrow] = b1.y; Bs[nb][lk + 6][lrow] = b1.z; Bs[nb][lk + 7][lrow] = b1.w;
            __syncthreads();
        }
    }

    // epilogue: ((x + b_ih) + hW) + b_hh, XLA pointwise (identical to R5), write c / h
#pragma unroll
    for (int i = 0; i < 8; i++) {
        int n = mb + ty * 8 + i;
        const float* hwp = &g_hw[(size_t)n * FD];
#pragma unroll
        for (int p = 0; p < 2; p++) {
            int dc = dcb + tx * 2 + p;
            float iv = __fadd_rn(__fadd_rn(__fadd_rn(acc[i][0 + p], bih[0 * Dd + dc]), hwp[0 * Dd + dc]), bhh[0 * Dd + dc]);
            float fv = __fadd_rn(__fadd_rn(__fadd_rn(acc[i][2 + p], bih[1 * Dd + dc]), hwp[1 * Dd + dc]), bhh[1 * Dd + dc]);
            float gv = __fadd_rn(__fadd_rn(__fadd_rn(acc[i][4 + p], bih[2 * Dd + dc]), hwp[2 * Dd + dc]), bhh[2 * Dd + dc]);
            float ov = __fadd_rn(__fadd_rn(__fadd_rn(acc[i][6 + p], bih[3 * Dd + dc]), hwp[3 * Dd + dc]), bhh[3 * Dd + dc]);
            float co = g_c[(size_t)n * Dd + dc];
            float cn = __fadd_rn(__fmul_rn(sig_xla(fv), co), __fmul_rn(sig_xla(iv), tanh_xla(gv)));
            float hn = __fadd_rn(__fmul_rn(sig_xla(ov), tanh_xla(cn)), f[(size_t)n * Dd + dc]);
            g_c[(size_t)n * Dd + dc] = cn;
            hout[(size_t)n * Dd + dc] = hn;
        }
    }
}

extern "C" void kernel_launch(void* const* d_in, const int* in_sizes, int n_in,
                              void* d_out, int out_size) {
    const float* f   = (const float*)d_in[0];
    const float* G   = (const float*)d_in[1];
    const float* Wih = (const float*)d_in[2];
    const float* Whh = (const float*)d_in[3];
    const float* bih = (const float*)d_in[4];
    const float* bhh = (const float*)d_in[5];
    float* out = (float*)d_out;

    k_init<<<(Nn * Dd) / 256, 256>>>(f);
    // P = f @ W_L^T  (B = Wih, row stride 1024)
    {
        float* Pp; cudaGetSymbolAddress((void**)&Pp, g_P);
        k_gemm<<<dim3(FD / 128, Nn / 128), 256>>>(f, 0, Wih, 1024, Pp);
    }
    float* hwp; cudaGetSymbolAddress((void**)&hwp, g_hw);

    for (int s = 0; s < Kk; s++) {
        k_attn<<<Nn / 32, 256>>>(s & 1, G);
        k_r<<<dim3(Dd / 128, Nn / 32), 256>>>(G);
        k_gemm<<<dim3(FD / 128, Nn / 128), 256>>>((const float*)0, s & 1, Whh, 512, hwp);
        k_gx<<<dim3(Dd / 32, Nn / 128), 256>>>(s & 1, Wih, bih, bhh, f, out, s == Kk - 1);
    }
}

// round 7
// speedup vs baseline: 1.2758x; 1.0940x over previous
#include <cuda_runtime.h>
#include <math.h>

#define Nn 8192
#define Kk 64
#define Dd 512
#define FD 2048   // 4*D

typedef unsigned long long u64t;

// ---- packed f32x2 ops (Blackwell FFMA2; each half = independent IEEE rn FMA) ----
#define PACKF2(d, lo, hi)  asm("mov.b64 %0, {%1, %2};" : "=l"(d) : "f"(lo), "f"(hi))
#define UNPACKF2(lo, hi, s) asm("mov.b64 {%0, %1}, %2;" : "=f"(lo), "=f"(hi) : "l"(s))
#define FMA2(d, a, b, c)   asm("fma.rn.f32x2 %0, %1, %2, %3;" : "=l"(d) : "l"(a), "l"(b), "l"(c))

// Scratch (allocation-free device globals)
__device__ float g_P[(size_t)Nn * FD];      // 64 MB: partial chain f@W_L^T (no biases)
__device__ float g_hw[(size_t)Nn * FD];     // 64 MB: h@W_hh^T per step
__device__ float g_h[2][(size_t)Nn * Dd];   // ping/pong h
__device__ float g_c[(size_t)Nn * Dd];      // cell state
__device__ float g_r[(size_t)Nn * Dd];      // r = a @ G
__device__ float g_a[(size_t)Nn * Kk];      // softmax weights

// ---- XLA EmitFastTanh f32 (verbatim) ----
__device__ __forceinline__ float tanh_xla(float x) {
    float ax = fabsf(x);
    float xc = fminf(fmaxf(x, -7.90531110763549805f), 7.90531110763549805f);
    float x2 = __fmul_rn(xc, xc);
    float p = -2.76076847742355e-16f;
    p = __fadd_rn(__fmul_rn(p, x2), 2.00018790482477e-13f);
    p = __fadd_rn(__fmul_rn(p, x2), -8.60467152213735e-11f);
    p = __fadd_rn(__fmul_rn(p, x2), 5.12229709037114e-08f);
    p = __fadd_rn(__fmul_rn(p, x2), 1.48572235717979e-05f);
    p = __fadd_rn(__fmul_rn(p, x2), 6.37261928875436e-04f);
    p = __fadd_rn(__fmul_rn(p, x2), 4.89352455891786e-03f);
    float num = __fmul_rn(xc, p);
    float q = 1.19825839466702e-06f;
    q = __fadd_rn(__fmul_rn(q, x2), 1.18534705686654e-04f);
    q = __fadd_rn(__fmul_rn(q, x2), 2.26843463243900e-03f);
    q = __fadd_rn(__fmul_rn(q, x2), 4.89352518554385e-03f);
    float r = __fdiv_rn(num, q);
    return (ax < 0.0004f) ? x : r;
}
__device__ __forceinline__ float sig_xla(float x) {
    return __fadd_rn(0.5f, __fmul_rn(0.5f, tanh_xla(__fmul_rn(0.5f, x))));
}

// ---------------- init: h0 = f, c = 0 ----------------
__global__ void k_init(const float* __restrict__ f) {
    int i = blockIdx.x * 256 + threadIdx.x;
    g_h[0][i] = f[i];
    g_c[i] = 0.f;
}

// ---------------- generic SGEMM via FFMA2: C[m][j] = serial-k chain A[m,:512].B[j,:512] ----------------
// 128x128 tile, 256 threads, 8x8/thread (4 col-pairs), double-buffered smem.
__global__ __launch_bounds__(256, 2) void k_gemm(const float* __restrict__ Aopt, int cur,
                                                 const float* __restrict__ B, long bstride,
                                                 float* __restrict__ C) {
    __shared__ float As[2][16][128];
    __shared__ float Bs[2][16][128];
    const float* __restrict__ A = Aopt ? Aopt : g_h[cur];
    const int jb = blockIdx.x * 128, mb = blockIdx.y * 128;
    const int tid = threadIdx.x, tx = tid & 15, ty = tid >> 4;
    const int lrow = tid >> 1, lk = (tid & 1) << 3;
    u64t acc2[8][4];
#pragma unroll
    for (int i = 0; i < 8; i++)
#pragma unroll
        for (int q = 0; q < 4; q++) acc2[i][q] = 0ull;

    const float* Arow = A + (size_t)(mb + lrow) * Dd + lk;
    const float* Brow = B + (size_t)(jb + lrow) * bstride + lk;

    float4 a0 = *(const float4*)(Arow), a1 = *(const float4*)(Arow + 4);
    float4 b0 = *(const float4*)(Brow), b1 = *(const float4*)(Brow + 4);
    As[0][lk + 0][lrow] = a0.x; As[0][lk + 1][lrow] = a0.y; As[0][lk + 2][lrow] = a0.z; As[0][lk + 3][lrow] = a0.w;
    As[0][lk + 4][lrow] = a1.x; As[0][lk + 5][lrow] = a1.y; As[0][lk + 6][lrow] = a1.z; As[0][lk + 7][lrow] = a1.w;
    Bs[0][lk + 0][lrow] = b0.x; Bs[0][lk + 1][lrow] = b0.y; Bs[0][lk + 2][lrow] = b0.z; Bs[0][lk + 3][lrow] = b0.w;
    Bs[0][lk + 4][lrow] = b1.x; Bs[0][lk + 5][lrow] = b1.y; Bs[0][lk + 6][lrow] = b1.z; Bs[0][lk + 7][lrow] = b1.w;
    __syncthreads();

    for (int kt = 0; kt < 32; kt++) {
        const int buf = kt & 1;
        if (kt < 31) {
            a0 = *(const float4*)(Arow + (kt + 1) * 16);
            a1 = *(const float4*)(Arow + (kt + 1) * 16 + 4);
            b0 = *(const float4*)(Brow + (kt + 1) * 16);
            b1 = *(const float4*)(Brow + (kt + 1) * 16 + 4);
        }
#pragma unroll
        for (int k = 0; k < 16; k++) {
            float ar[8], br[8];
            *(float4*)&ar[0] = *(const float4*)&As[buf][k][ty * 8];
            *(float4*)&ar[4] = *(const float4*)&As[buf][k][ty * 8 + 4];
            *(float4*)&br[0] = *(const float4*)&Bs[buf][k][tx * 8];
            *(float4*)&br[4] = *(const float4*)&Bs[buf][k][tx * 8 + 4];
            u64t ap[8], bp[4];
#pragma unroll
            for (int i = 0; i < 8; i++) PACKF2(ap[i], ar[i], ar[i]);
#pragma unroll
            for (int q = 0; q < 4; q++) PACKF2(bp[q], br[q * 2], br[q * 2 + 1]);
#pragma unroll
            for (int i = 0; i < 8; i++)
#pragma unroll
                for (int q = 0; q < 4; q++) FMA2(acc2[i][q], ap[i], bp[q], acc2[i][q]);
        }
        if (kt < 31) {
            const int nb = buf ^ 1;
            As[nb][lk + 0][lrow] = a0.x; As[nb][lk + 1][lrow] = a0.y; As[nb][lk + 2][lrow] = a0.z; As[nb][lk + 3][lrow] = a0.w;
            As[nb][lk + 4][lrow] = a1.x; As[nb][lk + 5][lrow] = a1.y; As[nb][lk + 6][lrow] = a1.z; As[nb][lk + 7][lrow] = a1.w;
            Bs[nb][lk + 0][lrow] = b0.x; Bs[nb][lk + 1][lrow] = b0.y; Bs[nb][lk + 2][lrow] = b0.z; Bs[nb][lk + 3][lrow] = b0.w;
            Bs[nb][lk + 4][lrow] = b1.x; Bs[nb][lk + 5][lrow] = b1.y; Bs[nb][lk + 6][lrow] = b1.z; Bs[nb][lk + 7][lrow] = b1.w;
            __syncthreads();
        }
    }
#pragma unroll
    for (int i = 0; i < 8; i++) {
        int n = mb + ty * 8 + i;
#pragma unroll
        for (int q = 0; q < 4; q++) {
            float lo, hi;
            UNPACKF2(lo, hi, acc2[i][q]);
            float2 v = make_float2(lo, hi);
            *(float2*)&C[(size_t)n * FD + jb + tx * 8 + q * 2] = v;
        }
    }
}

// ---------------- attention: logits chain + XLA softmax (verbatim R5/R6) ----------------
__global__ __launch_bounds__(256) void k_attn(int cur, const float* __restrict__ G) {
    __shared__ float Gs[Kk * 129];
    const float* __restrict__ h = g_h[cur];
    const int warp = threadIdx.x >> 5, lane = threadIdx.x & 31;
    const int n0 = blockIdx.x * 32 + warp * 4;
    float acc[4][2];
#pragma unroll
    for (int r = 0; r < 4; r++) { acc[r][0] = 0.f; acc[r][1] = 0.f; }

    for (int ch = 0; ch < 4; ch++) {
        __syncthreads();
        for (int e = threadIdx.x; e < Kk * 128; e += 256)
            Gs[(e >> 7) * 129 + (e & 127)] = G[(e >> 7) * Dd + ch * 128 + (e & 127)];
        __syncthreads();
#pragma unroll 2
        for (int d = 0; d < 128; d++) {
            float w0 = Gs[lane * 129 + d];
            float w1 = Gs[(lane + 32) * 129 + d];
#pragma unroll
            for (int r = 0; r < 4; r++) {
                float hv = h[(size_t)(n0 + r) * Dd + ch * 128 + d];
                acc[r][0] = fmaf(hv, w0, acc[r][0]);
                acc[r][1] = fmaf(hv, w1, acc[r][1]);
            }
        }
    }
#pragma unroll
    for (int r = 0; r < 4; r++) {
        float m = fmaxf(acc[r][0], acc[r][1]);
#pragma unroll
        for (int off = 16; off; off >>= 1) m = fmaxf(m, __shfl_xor_sync(0xffffffffu, m, off));
        float e0 = expf(acc[r][0] - m);
        float e1 = expf(acc[r][1] - m);
        float s = __fadd_rn(e0, e1);
#pragma unroll
        for (int off = 16; off; off >>= 1) s = __fadd_rn(s, __shfl_xor_sync(0xffffffffu, s, off));
        s = __shfl_sync(0xffffffffu, s, 0);
        g_a[(size_t)(n0 + r) * Kk + lane]      = __fdiv_rn(e0, s);
        g_a[(size_t)(n0 + r) * Kk + lane + 32] = __fdiv_rn(e1, s);
    }
}

// ---------------- r = a @ G : FFMA2, serial ascending k chain ----------------
__global__ __launch_bounds__(256) void k_r(const float* __restrict__ G) {
    __shared__ float Gs[Kk][128];
    __shared__ float as[32][Kk];
    const int d0 = blockIdx.x * 128, n0 = blockIdx.y * 32;
    const int tid = threadIdx.x;
    const int dthr = tid & 31, rgrp = tid >> 5;

    for (int e = tid; e < Kk * 128; e += 256)
        Gs[e >> 7][e & 127] = G[(size_t)(e >> 7) * Dd + d0 + (e & 127)];
    for (int e = tid; e < 32 * Kk; e += 256)
        as[e >> 6][e & 63] = g_a[(size_t)(n0 + (e >> 6)) * Kk + (e & 63)];
    __syncthreads();

    u64t acc2[4][2];
#pragma unroll
    for (int r = 0; r < 4; r++) { acc2[r][0] = 0ull; acc2[r][1] = 0ull; }
    for (int k = 0; k < Kk; k++) {
        float4 gv = *(const float4*)&Gs[k][dthr * 4];
        u64t g20, g21;
        PACKF2(g20, gv.x, gv.y);
        PACKF2(g21, gv.z, gv.w);
#pragma unroll
        for (int r = 0; r < 4; r++) {
            float av = as[rgrp * 4 + r][k];
            u64t a2;
            PACKF2(a2, av, av);
            FMA2(acc2[r][0], a2, g20, acc2[r][0]);
            FMA2(acc2[r][1], a2, g21, acc2[r][1]);
        }
    }
#pragma unroll
    for (int r = 0; r < 4; r++) {
        float x0, x1, x2, x3;
        UNPACKF2(x0, x1, acc2[r][0]);
        UNPACKF2(x2, x3, acc2[r][1]);
        float4 v = make_float4(x0, x1, x2, x3);
        *(float4*)&g_r[(size_t)(n0 + rgrp * 4 + r) * Dd + d0 + dthr * 4] = v;
    }
}

// ---------------- x-chain GEMM (resumed from g_P) via FFMA2 + fused LSTM epilogue ----------------
__global__ __launch_bounds__(256, 2) void k_gx(int cur, const float* __restrict__ Wih,
        const float* __restrict__ bih, const float* __restrict__ bhh,
        const float* __restrict__ f, float* __restrict__ dout, int last) {
    __shared__ float As[2][16][128];
    __shared__ float Bs[2][16][128];
    float* __restrict__ hout = last ? dout : g_h[cur ^ 1];
    const int dcb = blockIdx.x * 32, mb = blockIdx.y * 128;
    const int tid = threadIdx.x, tx = tid & 15, ty = tid >> 4;
    const int lrow = tid >> 1, lk = (tid & 1) << 3;
    const size_t bj = (size_t)((lrow >> 5) * Dd + dcb + (lrow & 31));

    const float* Arow = g_r + (size_t)(mb + lrow) * Dd + lk;
    const float* Brow = Wih + bj * 1024 + 512 + lk;

    // resume x-chain from P: col-pair q is gate q>>1? No — pairs are (g*2+p): pair index q covers gate g=q>>... 
    // thread cols: 4 gates x 2 dc; pair q = gate q (dc pair tx*2, tx*2+1)
    u64t acc2[8][4];
#pragma unroll
    for (int i = 0; i < 8; i++) {
        int n = mb + ty * 8 + i;
#pragma unroll
        for (int g = 0; g < 4; g++) {
            float2 v = *(const float2*)&g_P[(size_t)n * FD + g * Dd + dcb + tx * 2];
            PACKF2(acc2[i][g], v.x, v.y);
        }
    }

    float4 a0 = *(const float4*)(Arow), a1 = *(const float4*)(Arow + 4);
    float4 b0 = *(const float4*)(Brow), b1 = *(const float4*)(Brow + 4);
    As[0][lk + 0][lrow] = a0.x; As[0][lk + 1][lrow] = a0.y; As[0][lk + 2][lrow] = a0.z; As[0][lk + 3][lrow] = a0.w;
    As[0][lk + 4][lrow] = a1.x; As[0][lk + 5][lrow] = a1.y; As[0][lk + 6][lrow] = a1.z; As[0][lk + 7][lrow] = a1.w;
    Bs[0][lk + 0][lrow] = b0.x; Bs[0][lk + 1][lrow] = b0.y; Bs[0][lk + 2][lrow] = b0.z; Bs[0][lk + 3][lrow] = b0.w;
    Bs[0][lk + 4][lrow] = b1.x; Bs[0][lk + 5][lrow] = b1.y; Bs[0][lk + 6][lrow] = b1.z; Bs[0][lk + 7][lrow] = b1.w;
    __syncthreads();

    for (int kt = 0; kt < 32; kt++) {
        const int buf = kt & 1;
        if (kt < 31) {
            a0 = *(const float4*)(Arow + (kt + 1) * 16);
            a1 = *(const float4*)(Arow + (kt + 1) * 16 + 4);
            b0 = *(const float4*)(Brow + (kt + 1) * 16);
            b1 = *(const float4*)(Brow + (kt + 1) * 16 + 4);
        }
#pragma unroll
        for (int k = 0; k < 16; k++) {
            float ar[8], br[8];
            *(float4*)&ar[0] = *(const float4*)&As[buf][k][ty * 8];
            *(float4*)&ar[4] = *(const float4*)&As[buf][k][ty * 8 + 4];
#pragma unroll
            for (int g = 0; g < 4; g++)
                *(float2*)&br[g * 2] = *(const float2*)&Bs[buf][k][g * 32 + tx * 2];
            u64t ap[8], bp[4];
#pragma unroll
            for (int i = 0; i < 8; i++) PACKF2(ap[i], ar[i], ar[i]);
#pragma unroll
            for (int g = 0; g < 4; g++) PACKF2(bp[g], br[g * 2], br[g * 2 + 1]);
#pragma unroll
            for (int i = 0; i < 8; i++)
#pragma unroll
                for (int g = 0; g < 4; g++) FMA2(acc2[i][g], ap[i], bp[g], acc2[i][g]);
        }
        if (kt < 31) {
            const int nb = buf ^ 1;
            As[nb][lk + 0][lrow] = a0.x; As[nb][lk + 1][lrow] = a0.y; As[nb][lk + 2][lrow] = a0.z; As[nb][lk + 3][lrow] = a0.w;
            As[nb][lk + 4][lrow] = a1.x; As[nb][lk + 5][lrow] = a1.y; As[nb][lk + 6][lrow] = a1.z; As[nb][lk + 7][lrow] = a1.w;
            Bs[nb][lk + 0][lrow] = b0.x; Bs[nb][lk + 1][lrow] = b0.y; Bs[nb][lk + 2][lrow] = b0.z; Bs[nb][lk + 3][lrow] = b0.w;
            Bs[nb][lk + 4][lrow] = b1.x; Bs[nb][lk + 5][lrow] = b1.y; Bs[nb][lk + 6][lrow] = b1.z; Bs[nb][lk + 7][lrow] = b1.w;
            __syncthreads();
        }
    }

    // epilogue: ((x + b_ih) + hW) + b_hh, XLA pointwise (identical), write c / h
#pragma unroll
    for (int i = 0; i < 8; i++) {
        int n = mb + ty * 8 + i;
        const float* hwp = &g_hw[(size_t)n * FD];
        float ax[8];
#pragma unroll
        for (int g = 0; g < 4; g++) UNPACKF2(ax[g * 2], ax[g * 2 + 1], acc2[i][g]);
#pragma unroll
        for (int p = 0; p < 2; p++) {
            int dc = dcb + tx * 2 + p;
            float iv = __fadd_rn(__fadd_rn(__fadd_rn(ax[0 + p], bih[0 * Dd + dc]), hwp[0 * Dd + dc]), bhh[0 * Dd + dc]);
            float fv = __fadd_rn(__fadd_rn(__fadd_rn(ax[2 + p], bih[1 * Dd + dc]), hwp[1 * Dd + dc]), bhh[1 * Dd + dc]);
            float gv = __fadd_rn(__fadd_rn(__fadd_rn(ax[4 + p], bih[2 * Dd + dc]), hwp[2 * Dd + dc]), bhh[2 * Dd + dc]);
            float ov = __fadd_rn(__fadd_rn(__fadd_rn(ax[6 + p], bih[3 * Dd + dc]), hwp[3 * Dd + dc]), bhh[3 * Dd + dc]);
            float co = g_c[(size_t)n * Dd + dc];
            float cn = __fadd_rn(__fmul_rn(sig_xla(fv), co), __fmul_rn(sig_xla(iv), tanh_xla(gv)));
            float hn = __fadd_rn(__fmul_rn(sig_xla(ov), tanh_xla(cn)), f[(size_t)n * Dd + dc]);
            g_c[(size_t)n * Dd + dc] = cn;
            hout[(size_t)n * Dd + dc] = hn;
        }
    }
}

extern "C" void kernel_launch(void* const* d_in, const int* in_sizes, int n_in,
                              void* d_out, int out_size) {
    const float* f   = (const float*)d_in[0];
    const float* G   = (const float*)d_in[1];
    const float* Wih = (const float*)d_in[2];
    const float* Whh = (const float*)d_in[3];
    const float* bih = (const float*)d_in[4];
    const float* bhh = (const float*)d_in[5];
    float* out = (float*)d_out;

    k_init<<<(Nn * Dd) / 256, 256>>>(f);
    {
        float* Pp; cudaGetSymbolAddress((void**)&Pp, g_P);
        k_gemm<<<dim3(FD / 128, Nn / 128), 256>>>(f, 0, Wih, 1024, Pp);
    }
    float* hwp; cudaGetSymbolAddress((void**)&hwp, g_hw);

    for (int s = 0; s < Kk; s++) {
        k_attn<<<Nn / 32, 256>>>(s & 1, G);
        k_r<<<dim3(Dd / 128, Nn / 32), 256>>>(G);
        k_gemm<<<dim3(FD / 128, Nn / 128), 256>>>((const float*)0, s & 1, Whh, 512, hwp);
        k_gx<<<dim3(Dd / 32, Nn / 128), 256>>>(s & 1, Wih, bih, bhh, f, out, s == Kk - 1);
    }
}